// round 9
// baseline (speedup 1.0000x reference)
#include <cuda_runtime.h>
#include <math.h>
#include <stdint.h>

#define G 64      // B*T graphs
#define NN 1024   // nodes per graph
#define FF 64     // features
#define WP 72     // smem pitch (floats) for B tiles -> conflict-free LDS
#define AP 36     // adj smem pitch (words): 144B, 16B-aligned, conflict-free

// Scratch (device globals: allocation-free rule)
__device__ float g_Wh[G * NN * FF];   // 16 MB (tf32-rounded)
__device__ float g_s1[G * NN];
__device__ float g_s2[G * NN];

__device__ __forceinline__ float f2tf32(float x) {
    float r;
    asm("cvt.rna.tf32.f32 %0, %1;" : "=f"(r) : "f"(x));
    return r;
}
__device__ __forceinline__ uint32_t smem_u32(const void* p) {
    uint32_t a;
    asm("{ .reg .u64 t; cvta.to.shared.u64 t, %1; cvt.u32.u64 %0, t; }"
        : "=r"(a) : "l"(p));
    return a;
}
#define CP_ASYNC16(dst, src) \
    asm volatile("cp.async.cg.shared.global [%0], [%1], 16;" \
                 :: "r"(dst), "l"(src) : "memory")
#define CP_COMMIT() asm volatile("cp.async.commit_group;" ::: "memory")
#define CP_WAIT(n)  asm volatile("cp.async.wait_group %0;" :: "n"(n) : "memory")

#define MMA_TF32(acc, a0, a1, a2, a3, b0, b1) \
    asm volatile( \
        "mma.sync.aligned.m16n8k8.row.col.f32.tf32.tf32.f32 " \
        "{%0,%1,%2,%3}, {%4,%5,%6,%7}, {%8,%9}, {%0,%1,%2,%3};" \
        : "+f"((acc)[0]), "+f"((acc)[1]), "+f"((acc)[2]), "+f"((acc)[3]) \
        : "r"(a0), "r"(a1), "r"(a2), "r"(a3), "r"(b0), "r"(b1))

// ---------------------------------------------------------------------------
// Kernel P: Wh = h @ W via mma.sync (tf32-rounded); s1 = Wh@a1, s2 = Wh@a2.
// ---------------------------------------------------------------------------
__global__ __launch_bounds__(256) void prep_kernel(const float* __restrict__ h,
                                                   const float* __restrict__ W,
                                                   const float* __restrict__ a) {
    __shared__ float Ws[64 * WP];   // W tf32-rounded, [k][f]
    __shared__ float sA[128];       // a vector

    const int tid  = threadIdx.x;
    const int lane = tid & 31;
    const int w    = tid >> 5;

    #pragma unroll
    for (int i = 0; i < 16; i++) {
        int idx = tid + i * 256;              // 0..4095
        int k = idx >> 6, f = idx & 63;
        Ws[k * WP + f] = f2tf32(W[idx]);
    }
    if (tid < 128) sA[tid] = a[tid];
    __syncthreads();

    const int gq = lane >> 2;
    const int t  = lane & 3;
    const int r0 = blockIdx.x * 128 + w * 16 + gq;   // global node row
    const int r1 = r0 + 8;
    const float* h0 = h + (size_t)r0 * FF;
    const float* h1 = h + (size_t)r1 * FF;

    float acc[8][4];
    #pragma unroll
    for (int nt = 0; nt < 8; nt++)
        #pragma unroll
        for (int q = 0; q < 4; q++) acc[nt][q] = 0.f;

    #pragma unroll
    for (int ks = 0; ks < 8; ks++) {
        const int kb = ks * 8 + t;
        const uint32_t a0 = __float_as_uint(f2tf32(h0[kb]));
        const uint32_t a1 = __float_as_uint(f2tf32(h1[kb]));
        const uint32_t a2 = __float_as_uint(f2tf32(h0[kb + 4]));
        const uint32_t a3 = __float_as_uint(f2tf32(h1[kb + 4]));
        #pragma unroll
        for (int nt = 0; nt < 8; nt++) {
            const uint32_t b0 = __float_as_uint(Ws[kb * WP + nt * 8 + gq]);
            const uint32_t b1 = __float_as_uint(Ws[(kb + 4) * WP + nt * 8 + gq]);
            MMA_TF32(acc[nt], a0, a1, a2, a3, b0, b1);
        }
    }

    float s1_0 = 0.f, s2_0 = 0.f, s1_1 = 0.f, s2_1 = 0.f;
    float* o0 = g_Wh + (size_t)r0 * FF + 2 * t;
    float* o1 = g_Wh + (size_t)r1 * FF + 2 * t;
    #pragma unroll
    for (int nt = 0; nt < 8; nt++) {
        const int c = nt * 8 + 2 * t;
        const float a1c0 = sA[c],      a1c1 = sA[c + 1];
        const float a2c0 = sA[64 + c], a2c1 = sA[64 + c + 1];
        s1_0 += acc[nt][0] * a1c0 + acc[nt][1] * a1c1;
        s2_0 += acc[nt][0] * a2c0 + acc[nt][1] * a2c1;
        s1_1 += acc[nt][2] * a1c0 + acc[nt][3] * a1c1;
        s2_1 += acc[nt][2] * a2c0 + acc[nt][3] * a2c1;
        *(float2*)(o0 + nt * 8) = make_float2(f2tf32(acc[nt][0]), f2tf32(acc[nt][1]));
        *(float2*)(o1 + nt * 8) = make_float2(f2tf32(acc[nt][2]), f2tf32(acc[nt][3]));
    }
    #pragma unroll
    for (int off = 1; off <= 2; off <<= 1) {
        s1_0 += __shfl_xor_sync(0xffffffffu, s1_0, off);
        s2_0 += __shfl_xor_sync(0xffffffffu, s2_0, off);
        s1_1 += __shfl_xor_sync(0xffffffffu, s1_1, off);
        s2_1 += __shfl_xor_sync(0xffffffffu, s2_1, off);
    }
    if (t == 0) {
        g_s1[r0] = s1_0; g_s2[r0] = s2_0;
        g_s1[r1] = s1_1; g_s2[r1] = s2_1;
    }
}

// ---------------------------------------------------------------------------
// Kernel C: out[256,64] per CTA = softmax_mask(P) @ Wh, mma.sync m16n8k8 tf32.
// Raw adj streamed per chunk via cp.async (double-buffered, pitch AP).
// Z via ones-column MMA tile. Factorized exp tables. 512 thr, grid 256,
// 2 CTAs/SM -> single wave.
// ---------------------------------------------------------------------------
// dynamic smem (bytes):
//  tab    float4[1024]     @ 0      (16384)  {s2, e^{s2}, e^{0.2 s2}, 0}
//  adj0   u32[256*AP]      @ 16384  (36864)
//  adj1   u32[256*AP]      @ 53248  (36864)
//  Whs0   f32[32*WP]       @ 90112  (9216)
//  Whs1   f32[32*WP]       @ 99328  (9216)   total 108544
#define OFF_TAB  0
#define OFF_ADJ0 16384
#define OFF_ADJ1 53248
#define OFF_WHS0 90112
#define OFF_WHS1 99328
#define ATTN_SMEM 108544

extern __shared__ char smc[];

__global__ __launch_bounds__(512, 2) void attn_mma(const int* __restrict__ adj,
                                                   float* __restrict__ out) {
    float4* tab = (float4*)(smc + OFF_TAB);
    const uint32_t sb = smem_u32(smc);

    const int tid  = threadIdx.x;
    const int lane = tid & 31;
    const int w    = tid >> 5;          // 0..15
    const int gq   = lane >> 2;
    const int t    = lane & 3;
    const int gr   = blockIdx.x >> 2;
    const int i0   = (blockIdx.x & 3) << 8;   // 256-row tile

    const float* Whg  = g_Wh + (size_t)gr * NN * FF;
    const int*   adjg = adj + ((size_t)gr * NN + i0) * NN;

    const uint32_t adjoff[2] = { OFF_ADJ0, OFF_ADJ1 };
    const uint32_t whoff[2]  = { OFF_WHS0, OFF_WHS1 };

    // stage chunk 0: adj rows (thread -> row tid>>1, 4 segs) + Wh
    {
        const int r = tid >> 1, sg0 = (tid & 1) * 4;
        const int* src = adjg + (size_t)r * NN + sg0 * 4;
        const uint32_t dst = sb + OFF_ADJ0 + (uint32_t)(r * AP + sg0 * 4) * 4;
        #pragma unroll
        for (int q = 0; q < 4; q++) CP_ASYNC16(dst + q * 16, src + q * 4);
        const int k = tid >> 4, s4 = (tid & 15) * 4;
        CP_ASYNC16(sb + OFF_WHS0 + (uint32_t)(k * WP + s4) * 4, Whg + k * FF + s4);
        CP_COMMIT();
    }

    // exp table: 2 entries per thread
    {
        const float2 s2v = ((const float2*)(g_s2 + (size_t)gr * NN))[tid];
        tab[tid * 2 + 0] = make_float4(s2v.x, __expf(s2v.x), __expf(0.2f * s2v.x), 0.f);
        tab[tid * 2 + 1] = make_float4(s2v.y, __expf(s2v.y), __expf(0.2f * s2v.y), 0.f);
    }

    const int lr0 = w * 16 + gq;                 // CTA-local row (0..255)
    const int lr1 = lr0 + 8;
    const float s1_0 = g_s1[(size_t)gr * NN + i0 + lr0];
    const float s1_1 = g_s1[(size_t)gr * NN + i0 + lr1];
    const float e1_0 = __expf(s1_0), e1b_0 = __expf(0.2f * s1_0), thr0 = -s1_0;
    const float e1_1 = __expf(s1_1), e1b_1 = __expf(0.2f * s1_1), thr1 = -s1_1;

    float acc[9][4];
    #pragma unroll
    for (int nt = 0; nt < 9; nt++)
        #pragma unroll
        for (int q = 0; q < 4; q++) acc[nt][q] = 0.f;
    const uint32_t bz = (gq == 0) ? 0x3f800000u : 0u;   // ones-column B frag

    for (int jc = 0; jc < 32; jc++) {
        if (jc > 0) __syncthreads();   // all warps done with buf (jc+1)&1
        if (jc < 31) {                 // stage chunk jc+1
            const int s = (jc + 1) & 1;
            const int r = tid >> 1, sg0 = (tid & 1) * 4;
            const int* srcA = adjg + (size_t)r * NN + (jc + 1) * 32 + sg0 * 4;
            const uint32_t dstA = sb + adjoff[s] + (uint32_t)(r * AP + sg0 * 4) * 4;
            #pragma unroll
            for (int q = 0; q < 4; q++) CP_ASYNC16(dstA + q * 16, srcA + q * 4);
            const int k = tid >> 4, s4 = (tid & 15) * 4;
            CP_ASYNC16(sb + whoff[s] + (uint32_t)(k * WP + s4) * 4,
                       Whg + (jc + 1) * 32 * FF + k * FF + s4);
            CP_COMMIT();
            CP_WAIT(1);
        } else {
            CP_WAIT(0);
        }
        __syncthreads();

        const float*    Wc = (const float*)(smc + whoff[jc & 1]);
        const uint32_t* Ac = (const uint32_t*)(smc + adjoff[jc & 1]);
        const int j0 = jc * 32;

        #pragma unroll
        for (int ks = 0; ks < 4; ks++) {
            const int kb = ks * 8 + t;
            const float4 ta = tab[j0 + kb];
            const float4 tb = tab[j0 + kb + 4];
            const uint32_t am00 = Ac[lr0 * AP + kb];
            const uint32_t am01 = Ac[lr0 * AP + kb + 4];
            const uint32_t am10 = Ac[lr1 * AP + kb];
            const uint32_t am11 = Ac[lr1 * AP + kb + 4];

            const bool c00 = ta.x > thr0, c01 = tb.x > thr0;
            const bool c10 = ta.x > thr1, c11 = tb.x > thr1;
            float p00 = c00 ? e1_0 * ta.y : e1b_0 * ta.z;
            float p01 = c01 ? e1_0 * tb.y : e1b_0 * tb.z;
            float p10 = c10 ? e1_1 * ta.y : e1b_1 * ta.z;
            float p11 = c11 ? e1_1 * tb.y : e1b_1 * tb.z;
            p00 = am00 ? p00 : 0.f;
            p01 = am01 ? p01 : 0.f;
            p10 = am10 ? p10 : 0.f;
            p11 = am11 ? p11 : 0.f;

            const uint32_t a0 = __float_as_uint(p00);
            const uint32_t a1 = __float_as_uint(p10);
            const uint32_t a2 = __float_as_uint(p01);
            const uint32_t a3 = __float_as_uint(p11);

            #pragma unroll
            for (int nt = 0; nt < 8; nt++) {
                const uint32_t b0 = __float_as_uint(Wc[kb * WP + nt * 8 + gq]);
                const uint32_t b1 = __float_as_uint(Wc[(kb + 4) * WP + nt * 8 + gq]);
                MMA_TF32(acc[nt], a0, a1, a2, a3, b0, b1);
            }
            MMA_TF32(acc[8], a0, a1, a2, a3, bz, bz);   // Z tile
        }
    }

    // Z = col 64 (ones tile), held by t==0 lanes; broadcast within quad
    const float Z0 = __shfl_sync(0xffffffffu, acc[8][0], lane & 28);
    const float Z1 = __shfl_sync(0xffffffffu, acc[8][2], lane & 28);
    const float inv0 = 1.0f / Z0;
    const float inv1 = 1.0f / Z1;

    float* o0 = out + ((size_t)gr * NN + i0 + lr0) * FF + 2 * t;
    float* o1 = out + ((size_t)gr * NN + i0 + lr1) * FF + 2 * t;
    #pragma unroll
    for (int nt = 0; nt < 8; nt++) {
        float e0 = acc[nt][0] * inv0;
        float e1 = acc[nt][1] * inv0;
        float e2 = acc[nt][2] * inv1;
        float e3 = acc[nt][3] * inv1;
        e0 = e0 > 0.f ? e0 : expm1f(e0);
        e1 = e1 > 0.f ? e1 : expm1f(e1);
        e2 = e2 > 0.f ? e2 : expm1f(e2);
        e3 = e3 > 0.f ? e3 : expm1f(e3);
        *(float2*)(o0 + nt * 8) = make_float2(e0, e1);
        *(float2*)(o1 + nt * 8) = make_float2(e2, e3);
    }
}

// ---------------------------------------------------------------------------
extern "C" void kernel_launch(void* const* d_in, const int* in_sizes, int n_in,
                              void* d_out, int out_size) {
    const float* h   = (const float*)d_in[0];
    const int*   adj = (const int*)d_in[1];
    const float* W   = (const float*)d_in[2];
    const float* a   = (const float*)d_in[3];
    float* out = (float*)d_out;

    cudaFuncSetAttribute(attn_mma, cudaFuncAttributeMaxDynamicSharedMemorySize,
                         ATTN_SMEM);

    prep_kernel<<<512, 256>>>(h, W, a);
    attn_mma<<<G * 4, 512, ATTN_SMEM>>>(adj, out);
}